// round 9
// baseline (speedup 1.0000x reference)
#include <cuda_runtime.h>
#include <math.h>

#define NB 8
#define NC 128
#define NHW 9216
#define NS 576
#define ATT_SCALE 0.17677669529663687f  /* 1/sqrt(32) */

// ---------------- scratch (device globals; allocation forbidden) ----------------
__device__ float g_xr[NB*NS*NC], g_xi[NB*NS*NC];   // xhat tokens (b,s,c)
__device__ float g_qr[NB*NS*NC], g_qi[NB*NS*NC];
__device__ float g_kr[NB*NS*NC], g_ki[NB*NS*NC];
__device__ float g_vr[NB*NS*NC], g_vi[NB*NS*NC];
__device__ float g_ar[NB*NS*NC], g_ai[NB*NS*NC];   // attn output, (b,s,c) c=h*32+d
__device__ float g_or[NB*NS*NC], g_oi[NB*NS*NC];   // after o-projection
__device__ float g_attn[32*NS*NS];                 // logits/probs per (b*4+h)
__device__ float g_xrec[NB*NHW*NC];                // inverse transform (b,hw,c)
__device__ float g_mix[NB*NHW*NC];                 // gelu(LN(mixer)) (b,hw,c)

__device__ __forceinline__ float gelu_t(float x){
    float u = 0.7978845608028654f * (x + 0.044715f * x * x * x);
    return 0.5f * x * (1.0f + tanhf(u));
}

// ============================================================================
// 1) forward transform: xhat[b,s,c] = sum_hw x[b,c,hw] * (br,bi)[b,hw,s]
//    tile 64s x 64c, BK=16, micro 4x4, complex acc. grid (9,2,8).
// ============================================================================
__global__ void __launch_bounds__(256) k_fwd(const float* __restrict__ x,
        const float* __restrict__ br, const float* __restrict__ bi)
{
    __shared__ float sBr[16][68], sBi[16][68], sX[16][68];
    const int tid = threadIdx.x;
    const int s0 = blockIdx.x*64, c0 = blockIdx.y*64, b = blockIdx.z;
    const int lk = tid/16, ls4 = (tid%16)*4;        // basis loader
    const int lc = tid/4,  lx4 = (tid%4)*4;         // x loader
    const int ty = tid/16, tx = tid%16;             // compute map
    float ar[4][4], ai[4][4];
#pragma unroll
    for (int i=0;i<4;i++)
#pragma unroll
        for (int j=0;j<4;j++){ ar[i][j]=0.f; ai[i][j]=0.f; }

    for (int k0=0; k0<NHW; k0+=16){
        {
            int off = (b*NHW + k0 + lk)*NS + s0 + ls4;
            *(float4*)&sBr[lk][ls4] = *(const float4*)(br + off);
            *(float4*)&sBi[lk][ls4] = *(const float4*)(bi + off);
        }
        {
            float4 v = *(const float4*)(x + (b*NC + c0 + lc)*NHW + k0 + lx4);
            sX[lx4+0][lc]=v.x; sX[lx4+1][lc]=v.y; sX[lx4+2][lc]=v.z; sX[lx4+3][lc]=v.w;
        }
        __syncthreads();
#pragma unroll
        for (int kk=0; kk<16; kk++){
            float4 b4r = *(const float4*)&sBr[kk][ty*4];
            float4 b4i = *(const float4*)&sBi[kk][ty*4];
            float4 x4  = *(const float4*)&sX[kk][tx*4];
            float rr[4]={b4r.x,b4r.y,b4r.z,b4r.w};
            float ii[4]={b4i.x,b4i.y,b4i.z,b4i.w};
            float xx[4]={x4.x,x4.y,x4.z,x4.w};
#pragma unroll
            for (int i=0;i<4;i++)
#pragma unroll
                for (int j=0;j<4;j++){
                    ar[i][j] = fmaf(rr[i], xx[j], ar[i][j]);
                    ai[i][j] = fmaf(ii[i], xx[j], ai[i][j]);
                }
        }
        __syncthreads();
    }
#pragma unroll
    for (int i=0;i<4;i++){
        int off = (b*NS + s0 + ty*4 + i)*NC + c0 + tx*4;
        *(float4*)(g_xr + off) = make_float4(ar[i][0],ar[i][1],ar[i][2],ar[i][3]);
        *(float4*)(g_xi + off) = make_float4(ai[i][0],ai[i][1],ai[i][2],ai[i][3]);
    }
}

// ============================================================================
// 2) complex linear projection: out = in @ conj?no, wc.T + bc
//    which: 0/1/2 = q/k/v (in = xhat), 3 = o (in = attn-out).
//    tile 64s x 64o, K=128 (BK=16). grid (9,2,8).
// ============================================================================
__global__ void __launch_bounds__(256) k_cproj(const float* __restrict__ awr,
        const float* __restrict__ awi, const float* __restrict__ abr,
        const float* __restrict__ abi, int which)
{
    __shared__ float sTr[16][68], sTi[16][68], sWr[16][68], sWi[16][68];
    const int tid = threadIdx.x;
    const int s0 = blockIdx.x*64, o0 = blockIdx.y*64, b = blockIdx.z;
    const float *inr, *ini; float *outr, *outi;
    if (which==0){ inr=g_xr; ini=g_xi; outr=g_qr; outi=g_qi; }
    else if (which==1){ inr=g_xr; ini=g_xi; outr=g_kr; outi=g_ki; }
    else if (which==2){ inr=g_xr; ini=g_xi; outr=g_vr; outi=g_vi; }
    else { inr=g_ar; ini=g_ai; outr=g_or; outi=g_oi; }
    const float* wr = awr + which*NC*NC;
    const float* wi = awi + which*NC*NC;

    const int ls = tid/4, lk4 = (tid%4)*4;  // t loader (also w loader: lo = ls)
    const int ty = tid/16, tx = tid%16;
    float ar[4][4], ai[4][4];
#pragma unroll
    for (int i=0;i<4;i++)
#pragma unroll
        for (int j=0;j<4;j++){ ar[i][j]=0.f; ai[i][j]=0.f; }

    for (int k0=0; k0<NC; k0+=16){
        {
            int off = (b*NS + s0 + ls)*NC + k0 + lk4;
            float4 tr = *(const float4*)(inr + off);
            float4 ti = *(const float4*)(ini + off);
            sTr[lk4+0][ls]=tr.x; sTr[lk4+1][ls]=tr.y; sTr[lk4+2][ls]=tr.z; sTr[lk4+3][ls]=tr.w;
            sTi[lk4+0][ls]=ti.x; sTi[lk4+1][ls]=ti.y; sTi[lk4+2][ls]=ti.z; sTi[lk4+3][ls]=ti.w;
        }
        {
            int off = (o0 + ls)*NC + k0 + lk4;
            float4 a = *(const float4*)(wr + off);
            float4 c = *(const float4*)(wi + off);
            sWr[lk4+0][ls]=a.x; sWr[lk4+1][ls]=a.y; sWr[lk4+2][ls]=a.z; sWr[lk4+3][ls]=a.w;
            sWi[lk4+0][ls]=c.x; sWi[lk4+1][ls]=c.y; sWi[lk4+2][ls]=c.z; sWi[lk4+3][ls]=c.w;
        }
        __syncthreads();
#pragma unroll
        for (int kk=0; kk<16; kk++){
            float4 t4r = *(const float4*)&sTr[kk][ty*4];
            float4 t4i = *(const float4*)&sTi[kk][ty*4];
            float4 w4r = *(const float4*)&sWr[kk][tx*4];
            float4 w4i = *(const float4*)&sWi[kk][tx*4];
            float tr[4]={t4r.x,t4r.y,t4r.z,t4r.w};
            float ti[4]={t4i.x,t4i.y,t4i.z,t4i.w};
            float wrv[4]={w4r.x,w4r.y,w4r.z,w4r.w};
            float wiv[4]={w4i.x,w4i.y,w4i.z,w4i.w};
#pragma unroll
            for (int i=0;i<4;i++)
#pragma unroll
                for (int j=0;j<4;j++){
                    ar[i][j] = fmaf(tr[i], wrv[j], ar[i][j]);
                    ar[i][j] = fmaf(-ti[i], wiv[j], ar[i][j]);
                    ai[i][j] = fmaf(tr[i], wiv[j], ai[i][j]);
                    ai[i][j] = fmaf(ti[i], wrv[j], ai[i][j]);
                }
        }
        __syncthreads();
    }
    float4 b4r = *(const float4*)(abr + which*NC + o0 + tx*4);
    float4 b4i = *(const float4*)(abi + which*NC + o0 + tx*4);
    float brv[4]={b4r.x,b4r.y,b4r.z,b4r.w}, biv[4]={b4i.x,b4i.y,b4i.z,b4i.w};
#pragma unroll
    for (int i=0;i<4;i++){
        int off = (b*NS + s0 + ty*4 + i)*NC + o0 + tx*4;
        *(float4*)(outr + off) = make_float4(ar[i][0]+brv[0],ar[i][1]+brv[1],ar[i][2]+brv[2],ar[i][3]+brv[3]);
        *(float4*)(outi + off) = make_float4(ai[i][0]+biv[0],ai[i][1]+biv[1],ai[i][2]+biv[2],ai[i][3]+biv[3]);
    }
}

// ============================================================================
// 3) logits[bh,s,t] = scale * sum_d (qr*kr + qi*ki). tile 64x64, K=32. grid (9,9,32).
// ============================================================================
__global__ void __launch_bounds__(256) k_logits()
{
    __shared__ float sQr[32][68], sQi[32][68], sKr[32][68], sKi[32][68];
    const int tid = threadIdx.x;
    const int t0 = blockIdx.x*64, s0 = blockIdx.y*64, bh = blockIdx.z;
    const int b = bh>>2, h = bh&3;
    const int ls = tid/4, ld8 = (tid%4)*8;
    {
        int offq = (b*NS + s0 + ls)*NC + h*32 + ld8;
        int offk = (b*NS + t0 + ls)*NC + h*32 + ld8;
        float4 a0 = *(const float4*)(g_qr+offq), a1 = *(const float4*)(g_qr+offq+4);
        float4 b0 = *(const float4*)(g_qi+offq), b1 = *(const float4*)(g_qi+offq+4);
        float4 c0 = *(const float4*)(g_kr+offk), c1 = *(const float4*)(g_kr+offk+4);
        float4 d0 = *(const float4*)(g_ki+offk), d1 = *(const float4*)(g_ki+offk+4);
        sQr[ld8+0][ls]=a0.x; sQr[ld8+1][ls]=a0.y; sQr[ld8+2][ls]=a0.z; sQr[ld8+3][ls]=a0.w;
        sQr[ld8+4][ls]=a1.x; sQr[ld8+5][ls]=a1.y; sQr[ld8+6][ls]=a1.z; sQr[ld8+7][ls]=a1.w;
        sQi[ld8+0][ls]=b0.x; sQi[ld8+1][ls]=b0.y; sQi[ld8+2][ls]=b0.z; sQi[ld8+3][ls]=b0.w;
        sQi[ld8+4][ls]=b1.x; sQi[ld8+5][ls]=b1.y; sQi[ld8+6][ls]=b1.z; sQi[ld8+7][ls]=b1.w;
        sKr[ld8+0][ls]=c0.x; sKr[ld8+1][ls]=c0.y; sKr[ld8+2][ls]=c0.z; sKr[ld8+3][ls]=c0.w;
        sKr[ld8+4][ls]=c1.x; sKr[ld8+5][ls]=c1.y; sKr[ld8+6][ls]=c1.z; sKr[ld8+7][ls]=c1.w;
        sKi[ld8+0][ls]=d0.x; sKi[ld8+1][ls]=d0.y; sKi[ld8+2][ls]=d0.z; sKi[ld8+3][ls]=d0.w;
        sKi[ld8+4][ls]=d1.x; sKi[ld8+5][ls]=d1.y; sKi[ld8+6][ls]=d1.z; sKi[ld8+7][ls]=d1.w;
    }
    __syncthreads();
    const int ty = tid/16, tx = tid%16;
    float acc[4][4];
#pragma unroll
    for (int i=0;i<4;i++)
#pragma unroll
        for (int j=0;j<4;j++) acc[i][j]=0.f;
#pragma unroll
    for (int kk=0; kk<32; kk++){
        float4 q4r = *(const float4*)&sQr[kk][ty*4];
        float4 q4i = *(const float4*)&sQi[kk][ty*4];
        float4 k4r = *(const float4*)&sKr[kk][tx*4];
        float4 k4i = *(const float4*)&sKi[kk][tx*4];
        float qr[4]={q4r.x,q4r.y,q4r.z,q4r.w}, qi[4]={q4i.x,q4i.y,q4i.z,q4i.w};
        float kr[4]={k4r.x,k4r.y,k4r.z,k4r.w}, ki[4]={k4i.x,k4i.y,k4i.z,k4i.w};
#pragma unroll
        for (int i=0;i<4;i++)
#pragma unroll
            for (int j=0;j<4;j++){
                acc[i][j] = fmaf(qr[i], kr[j], acc[i][j]);
                acc[i][j] = fmaf(qi[i], ki[j], acc[i][j]);
            }
    }
#pragma unroll
    for (int i=0;i<4;i++){
        int off = (bh*NS + s0 + ty*4 + i)*NS + t0 + tx*4;
        *(float4*)(g_attn + off) = make_float4(acc[i][0]*ATT_SCALE, acc[i][1]*ATT_SCALE,
                                               acc[i][2]*ATT_SCALE, acc[i][3]*ATT_SCALE);
    }
}

// ============================================================================
// 4) softmax over last dim (576). warp per row, 8 rows/block. grid 2304.
// ============================================================================
__global__ void __launch_bounds__(256) k_softmax()
{
    const int row = blockIdx.x*8 + threadIdx.x/32;
    const int lane = threadIdx.x & 31;
    float* p = g_attn + row*NS;
    float e[18];
    float mx = -1e30f;
#pragma unroll
    for (int j=0;j<18;j++){ e[j] = p[lane + 32*j]; mx = fmaxf(mx, e[j]); }
#pragma unroll
    for (int o=16;o;o>>=1) mx = fmaxf(mx, __shfl_xor_sync(0xffffffffu, mx, o));
    float s = 0.f;
#pragma unroll
    for (int j=0;j<18;j++){ e[j] = __expf(e[j]-mx); s += e[j]; }
#pragma unroll
    for (int o=16;o;o>>=1) s += __shfl_xor_sync(0xffffffffu, s, o);
    float inv = 1.f/s;
#pragma unroll
    for (int j=0;j<18;j++) p[lane + 32*j] = e[j]*inv;
}

// ============================================================================
// 5) AV: o[b,s,h*32+d] = sum_t attn[bh,s,t]*v[b,t,h*32+d] (complex v).
//    tile 64s x 32d, BK=32. grid (9, 32).
// ============================================================================
__global__ void __launch_bounds__(256) k_av()
{
    __shared__ float sA[32][68], sVr[32][36], sVi[32][36];
    const int tid = threadIdx.x;
    const int s0 = blockIdx.x*64, bh = blockIdx.y;
    const int b = bh>>2, h = bh&3;
    const int la_s = tid/4, la_t8 = (tid%4)*8;
    const int lv_t = tid/8, lv_d4 = (tid%8)*4;
    const int sy = tid/8, dx = tid%8;
    float ar[2][4], ai[2][4];
#pragma unroll
    for (int i=0;i<2;i++)
#pragma unroll
        for (int j=0;j<4;j++){ ar[i][j]=0.f; ai[i][j]=0.f; }

    for (int t0=0; t0<NS; t0+=32){
        {
            int off = (bh*NS + s0 + la_s)*NS + t0 + la_t8;
            float4 a0 = *(const float4*)(g_attn+off), a1 = *(const float4*)(g_attn+off+4);
            sA[la_t8+0][la_s]=a0.x; sA[la_t8+1][la_s]=a0.y; sA[la_t8+2][la_s]=a0.z; sA[la_t8+3][la_s]=a0.w;
            sA[la_t8+4][la_s]=a1.x; sA[la_t8+5][la_s]=a1.y; sA[la_t8+6][la_s]=a1.z; sA[la_t8+7][la_s]=a1.w;
        }
        {
            int off = (b*NS + t0 + lv_t)*NC + h*32 + lv_d4;
            *(float4*)&sVr[lv_t][lv_d4] = *(const float4*)(g_vr + off);
            *(float4*)&sVi[lv_t][lv_d4] = *(const float4*)(g_vi + off);
        }
        __syncthreads();
#pragma unroll
        for (int kk=0; kk<32; kk++){
            float a0 = sA[kk][sy*2], a1 = sA[kk][sy*2+1];
            float4 v4r = *(const float4*)&sVr[kk][dx*4];
            float4 v4i = *(const float4*)&sVi[kk][dx*4];
            float vr[4]={v4r.x,v4r.y,v4r.z,v4r.w}, vi[4]={v4i.x,v4i.y,v4i.z,v4i.w};
#pragma unroll
            for (int j=0;j<4;j++){
                ar[0][j] = fmaf(a0, vr[j], ar[0][j]);
                ai[0][j] = fmaf(a0, vi[j], ai[0][j]);
                ar[1][j] = fmaf(a1, vr[j], ar[1][j]);
                ai[1][j] = fmaf(a1, vi[j], ai[1][j]);
            }
        }
        __syncthreads();
    }
#pragma unroll
    for (int i=0;i<2;i++){
        int off = (b*NS + s0 + sy*2 + i)*NC + h*32 + dx*4;
        *(float4*)(g_ar + off) = make_float4(ar[i][0],ar[i][1],ar[i][2],ar[i][3]);
        *(float4*)(g_ai + off) = make_float4(ai[i][0],ai[i][1],ai[i][2],ai[i][3]);
    }
}

// ============================================================================
// 6) inverse transform: x_rec[b,hw,c] = sum_s (or*br + oi*bi).
//    tile 64hw x 64c, BK=16. grid (144,2,8).
// ============================================================================
__global__ void __launch_bounds__(256) k_inv(const float* __restrict__ br,
                                             const float* __restrict__ bi)
{
    __shared__ float sBr[16][68], sBi[16][68], sOr[16][68], sOi[16][68];
    const int tid = threadIdx.x;
    const int m0 = blockIdx.x*64, c0 = blockIdx.y*64, b = blockIdx.z;
    const int lb_m = tid/4, lb_k4 = (tid%4)*4;
    const int lo_k = tid/16, lo_c4 = (tid%16)*4;
    const int my = tid/16, cx = tid%16;
    float acc[4][4];
#pragma unroll
    for (int i=0;i<4;i++)
#pragma unroll
        for (int j=0;j<4;j++) acc[i][j]=0.f;

    for (int k0=0; k0<NS; k0+=16){
        {
            int off = (b*NHW + m0 + lb_m)*NS + k0 + lb_k4;
            float4 r = *(const float4*)(br + off);
            float4 im = *(const float4*)(bi + off);
            sBr[lb_k4+0][lb_m]=r.x; sBr[lb_k4+1][lb_m]=r.y; sBr[lb_k4+2][lb_m]=r.z; sBr[lb_k4+3][lb_m]=r.w;
            sBi[lb_k4+0][lb_m]=im.x; sBi[lb_k4+1][lb_m]=im.y; sBi[lb_k4+2][lb_m]=im.z; sBi[lb_k4+3][lb_m]=im.w;
        }
        {
            int off = (b*NS + k0 + lo_k)*NC + c0 + lo_c4;
            *(float4*)&sOr[lo_k][lo_c4] = *(const float4*)(g_or + off);
            *(float4*)&sOi[lo_k][lo_c4] = *(const float4*)(g_oi + off);
        }
        __syncthreads();
#pragma unroll
        for (int kk=0; kk<16; kk++){
            float4 b4r = *(const float4*)&sBr[kk][my*4];
            float4 b4i = *(const float4*)&sBi[kk][my*4];
            float4 o4r = *(const float4*)&sOr[kk][cx*4];
            float4 o4i = *(const float4*)&sOi[kk][cx*4];
            float brv[4]={b4r.x,b4r.y,b4r.z,b4r.w}, biv[4]={b4i.x,b4i.y,b4i.z,b4i.w};
            float orv[4]={o4r.x,o4r.y,o4r.z,o4r.w}, oiv[4]={o4i.x,o4i.y,o4i.z,o4i.w};
#pragma unroll
            for (int i=0;i<4;i++)
#pragma unroll
                for (int j=0;j<4;j++){
                    acc[i][j] = fmaf(brv[i], orv[j], acc[i][j]);
                    acc[i][j] = fmaf(biv[i], oiv[j], acc[i][j]);
                }
        }
        __syncthreads();
    }
#pragma unroll
    for (int i=0;i<4;i++){
        int off = (b*NHW + m0 + my*4 + i)*NC + c0 + cx*4;
        *(float4*)(g_xrec + off) = make_float4(acc[i][0],acc[i][1],acc[i][2],acc[i][3]);
    }
}

// ============================================================================
// 7) alpha-scale + mixer GEMM + bias + LayerNorm + gelu. 32 rows/block. grid 2304.
// ============================================================================
__global__ void __launch_bounds__(256) k_mixln(const float* __restrict__ alpha,
        const float* __restrict__ mw, const float* __restrict__ mb,
        const float* __restrict__ ng, const float* __restrict__ nbeta)
{
    __shared__ float sW[32][132], sIn[32][36];
    const int tid = threadIdx.x;
    const int row0 = blockIdx.x*32;
    const int lw_c = tid/2, lw_k16 = (tid%2)*16;
    const int li_r = tid/8, li_k4 = (tid%8)*4;
    const int r4 = (tid/32)*4, c4 = (tid%32)*4;
    float acc[4][4];
#pragma unroll
    for (int i=0;i<4;i++)
#pragma unroll
        for (int j=0;j<4;j++) acc[i][j]=0.f;

    for (int k0=0; k0<NC; k0+=32){
#pragma unroll
        for (int q=0;q<4;q++){
            float4 w = *(const float4*)(mw + lw_c*NC + k0 + lw_k16 + q*4);
            sW[lw_k16+q*4+0][lw_c]=w.x; sW[lw_k16+q*4+1][lw_c]=w.y;
            sW[lw_k16+q*4+2][lw_c]=w.z; sW[lw_k16+q*4+3][lw_c]=w.w;
        }
        {
            float4 v = *(const float4*)(g_xrec + (row0 + li_r)*NC + k0 + li_k4);
            float4 al = *(const float4*)(alpha + k0 + li_k4);
            sIn[li_r][li_k4+0]=v.x*al.x; sIn[li_r][li_k4+1]=v.y*al.y;
            sIn[li_r][li_k4+2]=v.z*al.z; sIn[li_r][li_k4+3]=v.w*al.w;
        }
        __syncthreads();
#pragma unroll
        for (int kk=0; kk<32; kk++){
            float4 w4 = *(const float4*)&sW[kk][c4];
            float wv[4]={w4.x,w4.y,w4.z,w4.w};
#pragma unroll
            for (int i=0;i<4;i++){
                float xv = sIn[r4+i][kk];
#pragma unroll
                for (int j=0;j<4;j++) acc[i][j] = fmaf(xv, wv[j], acc[i][j]);
            }
        }
        __syncthreads();
    }
    float4 mb4 = *(const float4*)(mb + c4);
    float4 g4 = *(const float4*)(ng + c4);
    float4 be4 = *(const float4*)(nbeta + c4);
    float mbv[4]={mb4.x,mb4.y,mb4.z,mb4.w}, gv[4]={g4.x,g4.y,g4.z,g4.w}, bev[4]={be4.x,be4.y,be4.z,be4.w};
#pragma unroll
    for (int i=0;i<4;i++){
        float s1=0.f, s2=0.f;
#pragma unroll
        for (int j=0;j<4;j++){ float v = acc[i][j]+mbv[j]; acc[i][j]=v; s1+=v; s2+=v*v; }
#pragma unroll
        for (int o=16;o;o>>=1){ s1 += __shfl_xor_sync(0xffffffffu,s1,o); s2 += __shfl_xor_sync(0xffffffffu,s2,o); }
        float mu = s1*(1.f/NC);
        float var = s2*(1.f/NC) - mu*mu;
        float rs = rsqrtf(var + 1e-5f);
        float outv[4];
#pragma unroll
        for (int j=0;j<4;j++) outv[j] = gelu_t((acc[i][j]-mu)*rs*gv[j] + bev[j]);
        *(float4*)(g_mix + (row0 + r4 + i)*NC + c4) = make_float4(outv[0],outv[1],outv[2],outv[3]);
    }
}

// ============================================================================
// 8) final: out[b,o,hw] = gelu(mix[b,hw,o] + x@shortcut). tile 64hw x 64o. grid (144,2,8).
// ============================================================================
__global__ void __launch_bounds__(256) k_final(const float* __restrict__ x,
        const float* __restrict__ sw, const float* __restrict__ sb, float* __restrict__ out)
{
    __shared__ float sW[16][68], sX[16][68];
    __shared__ float sM[64][68];
    const int tid = threadIdx.x;
    const int hw0 = blockIdx.x*64, o0 = blockIdx.y*64, b = blockIdx.z;
    const int lw_o = tid/4, lw_k4 = (tid%4)*4;
    const int lx_k = tid/16, lx_h4 = (tid%16)*4;
    const int oy = tid/16, hx = tid%16;
    float acc[4][4];
#pragma unroll
    for (int i=0;i<4;i++)
#pragma unroll
        for (int j=0;j<4;j++) acc[i][j]=0.f;

    for (int k0=0; k0<NC; k0+=16){
        {
            float4 w = *(const float4*)(sw + (o0 + lw_o)*NC + k0 + lw_k4);
            sW[lw_k4+0][lw_o]=w.x; sW[lw_k4+1][lw_o]=w.y; sW[lw_k4+2][lw_o]=w.z; sW[lw_k4+3][lw_o]=w.w;
        }
        *(float4*)&sX[lx_k][lx_h4] = *(const float4*)(x + (b*NC + k0 + lx_k)*NHW + hw0 + lx_h4);
        __syncthreads();
#pragma unroll
        for (int kk=0; kk<16; kk++){
            float4 w4 = *(const float4*)&sW[kk][oy*4];
            float4 x4 = *(const float4*)&sX[kk][hx*4];
            float wv[4]={w4.x,w4.y,w4.z,w4.w}, xv[4]={x4.x,x4.y,x4.z,x4.w};
#pragma unroll
            for (int i=0;i<4;i++)
#pragma unroll
                for (int j=0;j<4;j++) acc[i][j] = fmaf(wv[i], xv[j], acc[i][j]);
        }
        __syncthreads();
    }
    // stage mix tile (coalesced) then add transposed
    {
        const int mr = tid/16, mc4 = (tid%16)*4;
#pragma unroll
        for (int it=0; it<4; it++)
            *(float4*)&sM[mr + it*16][mc4] =
                *(const float4*)(g_mix + (b*NHW + hw0 + mr + it*16)*NC + o0 + mc4);
    }
    __syncthreads();
    float4 sb4 = *(const float4*)(sb + o0 + oy*4);
    float sbv[4]={sb4.x,sb4.y,sb4.z,sb4.w};
#pragma unroll
    for (int i=0;i<4;i++){
        float v[4];
#pragma unroll
        for (int j=0;j<4;j++)
            v[j] = gelu_t(acc[i][j] + sbv[i] + sM[hx*4+j][oy*4+i]);
        *(float4*)(out + (b*NC + o0 + oy*4 + i)*NHW + hw0 + hx*4) = make_float4(v[0],v[1],v[2],v[3]);
    }
}

// ============================================================================
extern "C" void kernel_launch(void* const* d_in, const int* in_sizes, int n_in,
                              void* d_out, int out_size)
{
    const float* x     = (const float*)d_in[0];
    const float* br    = (const float*)d_in[1];
    const float* bi    = (const float*)d_in[2];
    const float* awr   = (const float*)d_in[3];
    const float* awi   = (const float*)d_in[4];
    const float* abr   = (const float*)d_in[5];
    const float* abi   = (const float*)d_in[6];
    const float* alpha = (const float*)d_in[7];
    const float* mw    = (const float*)d_in[8];
    const float* mb    = (const float*)d_in[9];
    const float* ng    = (const float*)d_in[10];
    const float* nbeta = (const float*)d_in[11];
    const float* sw    = (const float*)d_in[12];
    const float* sb    = (const float*)d_in[13];
    float* out = (float*)d_out;

    k_fwd<<<dim3(9,2,NB), 256>>>(x, br, bi);
    k_cproj<<<dim3(9,2,NB), 256>>>(awr, awi, abr, abi, 0);
    k_cproj<<<dim3(9,2,NB), 256>>>(awr, awi, abr, abi, 1);
    k_cproj<<<dim3(9,2,NB), 256>>>(awr, awi, abr, abi, 2);
    k_logits<<<dim3(9,9,32), 256>>>();
    k_softmax<<<dim3(32*NS/8), 256>>>();
    k_av<<<dim3(9,32), 256>>>();
    k_cproj<<<dim3(9,2,NB), 256>>>(awr, awi, abr, abi, 3);
    k_inv<<<dim3(144,2,NB), 256>>>(br, bi);
    k_mixln<<<dim3(NB*NHW/32), 256>>>(alpha, mw, mb, ng, nbeta);
    k_final<<<dim3(144,2,NB), 256>>>(x, sw, sb, out);
}